// round 1
// baseline (speedup 1.0000x reference)
#include <cuda_runtime.h>
#include <cuda_bf16.h>

#define N_NODES 50000
#define N_EDGES 800000
#define N_GRAPHS 64
#define EMB_DIM 128
#define IMG_DIM 4096
#define N_TYPES 30
#define CAT_DIM (IMG_DIM + EMB_DIM)   // 4224

// ---------------- scratch (device globals; no allocation allowed) -------------
__device__ float g_dis[N_NODES];          // deg then rsqrt(deg)
__device__ int   g_cnt_e[N_NODES];
__device__ int   g_offs[N_NODES + 1];
__device__ int   g_cursor[N_NODES];
__device__ int   g_erow[N_EDGES];
__device__ float g_ec[N_EDGES];

__device__ float g_XW[N_NODES * EMB_DIM];
__device__ float g_bufA[N_NODES * EMB_DIM];
__device__ float g_bufB[N_NODES * EMB_DIM];
__device__ float g_TXW[N_TYPES * EMB_DIM];

__device__ float g_xc[N_GRAPHS * CAT_DIM];     // [xi | pooled]
__device__ float g_oi[N_GRAPHS * EMB_DIM];
__device__ float g_oc[N_GRAPHS * EMB_DIM];
__device__ float g_pooled[N_GRAPHS * EMB_DIM];
__device__ float g_cntb[N_GRAPHS];

// ---------------- init ---------------------------------------------------------
__global__ void k_init() {
    int i = blockIdx.x * blockDim.x + threadIdx.x;
    if (i < N_NODES) { g_dis[i] = 1.0f; g_cnt_e[i] = 0; g_cursor[i] = 0; }
    if (i < N_GRAPHS) g_cntb[i] = 0.f;
    if (i < N_GRAPHS * EMB_DIM) g_pooled[i] = 0.f;
}

// deg[col] += ew ; count[col]++
__global__ void k_deg(const int* __restrict__ ei, const float* __restrict__ ea) {
    int e = blockIdx.x * blockDim.x + threadIdx.x;
    if (e >= N_EDGES) return;
    int c = ei[N_EDGES + e];
    atomicAdd(&g_dis[c], ea[e]);
    atomicAdd(&g_cnt_e[c], 1);
}

__global__ void k_rsqrt() {
    int i = blockIdx.x * blockDim.x + threadIdx.x;
    if (i < N_NODES) g_dis[i] = rsqrtf(g_dis[i]);
}

// single-block exclusive scan of g_cnt_e -> g_offs
__global__ void k_scan() {
    __shared__ int sh[1024];
    __shared__ int carry;
    if (threadIdx.x == 0) carry = 0;
    __syncthreads();
    for (int base = 0; base < N_NODES; base += 1024) {
        int i = base + (int)threadIdx.x;
        int v = (i < N_NODES) ? g_cnt_e[i] : 0;
        sh[threadIdx.x] = v;
        __syncthreads();
        for (int off = 1; off < 1024; off <<= 1) {
            int t = (threadIdx.x >= off) ? sh[threadIdx.x - off] : 0;
            __syncthreads();
            sh[threadIdx.x] += t;
            __syncthreads();
        }
        if (i < N_NODES) g_offs[i] = carry + sh[threadIdx.x] - v;
        int tot = sh[1023];
        __syncthreads();
        if (threadIdx.x == 0) carry += tot;
        __syncthreads();
    }
    if (threadIdx.x == 0) g_offs[N_NODES] = carry;
}

// scatter edges into CSR order, with precomputed coefficient
__global__ void k_scatter(const int* __restrict__ ei, const float* __restrict__ ea) {
    int e = blockIdx.x * blockDim.x + threadIdx.x;
    if (e >= N_EDGES) return;
    int r = ei[e], c = ei[N_EDGES + e];
    float coef = g_dis[r] * ea[e] * g_dis[c];
    int pos = g_offs[c] + atomicAdd(&g_cursor[c], 1);
    g_erow[pos] = r;
    g_ec[pos] = coef;
}

// TXW[t][d] = sum_k emb[t][k] * W1[d][k]   (30 x 128 x 128)
__global__ void k_table_gemm(const float* __restrict__ emb, const float* __restrict__ W1) {
    __shared__ float xr[EMB_DIM];
    int t = blockIdx.x, d = threadIdx.x;
    xr[d] = emb[t * EMB_DIM + d];
    __syncthreads();
    const float* w = &W1[d * EMB_DIM];
    float s = 0.f;
    #pragma unroll 8
    for (int k = 0; k < EMB_DIM; k++) s += xr[k] * w[k];
    g_TXW[t * EMB_DIM + d] = s;
}

// XW[i] = TXW[type[i]]
__global__ void k_gather(const int* __restrict__ types) {
    int t = blockIdx.x * blockDim.x + threadIdx.x;      // N*32 threads, float4 each
    if (t >= N_NODES * 32) return;
    int i = t >> 5, j = (t & 31) << 2;
    *(float4*)&g_XW[i * EMB_DIM + j] = *(const float4*)&g_TXW[types[i] * EMB_DIM + j];
}

// warp-per-node CSR aggregation: out = sum c*xw[row] + dis^2*xw[node] + bias
__global__ void k_agg(const float* __restrict__ xw, const float* __restrict__ bias,
                      float* __restrict__ out) {
    int node = blockIdx.x * 8 + (threadIdx.x >> 5);
    if (node >= N_NODES) return;
    int lane = threadIdx.x & 31;
    float4 acc = make_float4(0.f, 0.f, 0.f, 0.f);
    int s = g_offs[node], e = g_offs[node + 1];
    for (int p = s; p < e; p++) {
        int r = g_erow[p];
        float c = g_ec[p];
        float4 v = *(const float4*)&xw[r * EMB_DIM + lane * 4];
        acc.x += c * v.x; acc.y += c * v.y; acc.z += c * v.z; acc.w += c * v.w;
    }
    float d2 = g_dis[node]; d2 *= d2;
    float4 v = *(const float4*)&xw[node * EMB_DIM + lane * 4];
    float4 b = *(const float4*)&bias[lane * 4];
    acc.x += d2 * v.x + b.x; acc.y += d2 * v.y + b.y;
    acc.z += d2 * v.z + b.z; acc.w += d2 * v.w + b.w;
    *(float4*)&out[node * EMB_DIM + lane * 4] = acc;
}

// mean-pool numerator + counts via atomics
__global__ void k_pool(const float* __restrict__ xg, const int* __restrict__ batch) {
    int node = blockIdx.x * 8 + (threadIdx.x >> 5);
    if (node >= N_NODES) return;
    int lane = threadIdx.x & 31;
    int b = batch[node];
    if (lane == 0) atomicAdd(&g_cntb[b], 1.f);
    float4 v = *(const float4*)&xg[node * EMB_DIM + lane * 4];
    float* p = &g_pooled[b * EMB_DIM + lane * 4];
    atomicAdd(p + 0, v.x); atomicAdd(p + 1, v.y);
    atomicAdd(p + 2, v.z); atomicAdd(p + 3, v.w);
}

__global__ void k_pool_div() {
    int i = blockIdx.x * blockDim.x + threadIdx.x;
    if (i >= N_GRAPHS * EMB_DIM) return;
    int m = i >> 7, d = i & 127;
    float c = fmaxf(g_cntb[m], 1.f);
    g_xc[m * CAT_DIM + IMG_DIM + d] = g_pooled[i] / c;
}

// ---------------- generic SGEMM: C = A(MxK) * B(NxK)^T (+bias), 64x64 tile ----
template <bool RELU_A>
__global__ void __launch_bounds__(256)
k_sgemm(const float* __restrict__ A, int lda,
        const float* __restrict__ B, int ldb,
        const float* __restrict__ bias,
        float* __restrict__ C, int ldc,
        int M, int N, int K) {
    __shared__ float As[16][68];
    __shared__ float Bs[16][68];
    int t = threadIdx.x;
    int tn = t & 15, tm = t >> 4;          // 16 x 16 thread grid, 4x4 micro-tile
    int m0 = blockIdx.y * 64, n0 = blockIdx.x * 64;
    int lrow = t >> 2, lkq = (t & 3) << 2; // loader: row 0..63, k-quad

    float c[4][4];
    #pragma unroll
    for (int i = 0; i < 4; i++)
        #pragma unroll
        for (int j = 0; j < 4; j++) c[i][j] = 0.f;

    for (int k0 = 0; k0 < K; k0 += 16) {
        // load A tile (64 x 16), transposed into As[k][m]
        float4 a;
        int am = m0 + lrow;
        if (am < M) a = *(const float4*)&A[(size_t)am * lda + k0 + lkq];
        else        a = make_float4(0.f, 0.f, 0.f, 0.f);
        if (RELU_A) {
            a.x = fmaxf(a.x, 0.f); a.y = fmaxf(a.y, 0.f);
            a.z = fmaxf(a.z, 0.f); a.w = fmaxf(a.w, 0.f);
        }
        As[lkq + 0][lrow] = a.x; As[lkq + 1][lrow] = a.y;
        As[lkq + 2][lrow] = a.z; As[lkq + 3][lrow] = a.w;
        // load B tile (64 x 16), transposed into Bs[k][n]
        int bn = n0 + lrow;
        float4 b;
        if (bn < N) b = *(const float4*)&B[(size_t)bn * ldb + k0 + lkq];
        else        b = make_float4(0.f, 0.f, 0.f, 0.f);
        Bs[lkq + 0][lrow] = b.x; Bs[lkq + 1][lrow] = b.y;
        Bs[lkq + 2][lrow] = b.z; Bs[lkq + 3][lrow] = b.w;
        __syncthreads();
        #pragma unroll
        for (int k = 0; k < 16; k++) {
            float4 af = *(const float4*)&As[k][tm * 4];
            float4 bf = *(const float4*)&Bs[k][tn * 4];
            c[0][0] += af.x * bf.x; c[0][1] += af.x * bf.y; c[0][2] += af.x * bf.z; c[0][3] += af.x * bf.w;
            c[1][0] += af.y * bf.x; c[1][1] += af.y * bf.y; c[1][2] += af.y * bf.z; c[1][3] += af.y * bf.w;
            c[2][0] += af.z * bf.x; c[2][1] += af.z * bf.y; c[2][2] += af.z * bf.z; c[2][3] += af.z * bf.w;
            c[3][0] += af.w * bf.x; c[3][1] += af.w * bf.y; c[3][2] += af.w * bf.z; c[3][3] += af.w * bf.w;
        }
        __syncthreads();
    }
    #pragma unroll
    for (int i = 0; i < 4; i++) {
        int m = m0 + tm * 4 + i;
        if (m >= M) continue;
        #pragma unroll
        for (int j = 0; j < 4; j++) {
            int n = n0 + tn * 4 + j;
            float v = c[i][j];
            if (bias) v += bias[n];
            C[(size_t)m * ldc + n] = v;
        }
    }
}

// row L2-normalize 64x128 and write to output
__global__ void k_norm(const float* __restrict__ src, float* __restrict__ dst) {
    __shared__ float sh[4];
    int m = blockIdx.x;
    float v = src[m * EMB_DIM + threadIdx.x];
    float s = v * v;
    #pragma unroll
    for (int o = 16; o; o >>= 1) s += __shfl_xor_sync(0xffffffffu, s, o);
    if ((threadIdx.x & 31) == 0) sh[threadIdx.x >> 5] = s;
    __syncthreads();
    float tot = sh[0] + sh[1] + sh[2] + sh[3];
    dst[m * EMB_DIM + threadIdx.x] = v * rsqrtf(tot);
}

// ---------------- host ---------------------------------------------------------
extern "C" void kernel_launch(void* const* d_in, const int* in_sizes, int n_in,
                              void* d_out, int out_size) {
    const float* images  = (const float*)d_in[0];
    const int*   ntypes  = (const int*)  d_in[1];
    const int*   eidx    = (const int*)  d_in[2];
    const float* eattr   = (const float*)d_in[3];
    const int*   batch   = (const int*)  d_in[4];
    const float* emb     = (const float*)d_in[5];
    const float* W_img   = (const float*)d_in[6];
    const float* b_img   = (const float*)d_in[7];
    const float* W1      = (const float*)d_in[8];
    const float* b1      = (const float*)d_in[9];
    const float* W2      = (const float*)d_in[10];
    const float* b2      = (const float*)d_in[11];
    const float* W3      = (const float*)d_in[12];
    const float* b3      = (const float*)d_in[13];
    const float* Wi      = (const float*)d_in[14];
    const float* bi      = (const float*)d_in[15];
    const float* Wc      = (const float*)d_in[16];
    const float* bc      = (const float*)d_in[17];
    float* out = (float*)d_out;

    float *p_XW, *p_bufA, *p_bufB, *p_xc, *p_oi, *p_oc;
    float *p_b1, *p_b2, *p_b3;
    cudaGetSymbolAddress((void**)&p_XW,   g_XW);
    cudaGetSymbolAddress((void**)&p_bufA, g_bufA);
    cudaGetSymbolAddress((void**)&p_bufB, g_bufB);
    cudaGetSymbolAddress((void**)&p_xc,   g_xc);
    cudaGetSymbolAddress((void**)&p_oi,   g_oi);
    cudaGetSymbolAddress((void**)&p_oc,   g_oc);
    p_b1 = (float*)b1; p_b2 = (float*)b2; p_b3 = (float*)b3;

    const int T256 = 256;
    int nb_nodes = (N_NODES + T256 - 1) / T256;
    int nb_edges = (N_EDGES + T256 - 1) / T256;
    int nb_warp8 = (N_NODES + 7) / 8;

    // graph preprocessing
    k_init<<<nb_nodes, T256>>>();
    k_deg<<<nb_edges, T256>>>(eidx, eattr);
    k_rsqrt<<<nb_nodes, T256>>>();
    k_scan<<<1, 1024>>>();
    k_scatter<<<nb_edges, T256>>>(eidx, eattr);

    // image branch: xi -> g_xc[:, 0:4096]
    k_sgemm<false><<<dim3(IMG_DIM / 64, 1), 256>>>(images, IMG_DIM, W_img, IMG_DIM,
                                                   b_img, p_xc, CAT_DIM, N_GRAPHS, IMG_DIM, IMG_DIM);

    // layer 1 via table GEMM + gather
    k_table_gemm<<<N_TYPES, EMB_DIM>>>(emb, W1);
    k_gather<<<(N_NODES * 32 + T256 - 1) / T256, T256>>>(ntypes);
    k_agg<<<nb_warp8, T256>>>(p_XW, p_b1, p_bufA);

    // layer 2
    k_sgemm<true><<<dim3(EMB_DIM / 64, (N_NODES + 63) / 64), 256>>>(p_bufA, EMB_DIM, W2, EMB_DIM,
                                                                    nullptr, p_XW, EMB_DIM,
                                                                    N_NODES, EMB_DIM, EMB_DIM);
    k_agg<<<nb_warp8, T256>>>(p_XW, p_b2, p_bufB);

    // layer 3
    k_sgemm<true><<<dim3(EMB_DIM / 64, (N_NODES + 63) / 64), 256>>>(p_bufB, EMB_DIM, W3, EMB_DIM,
                                                                    nullptr, p_XW, EMB_DIM,
                                                                    N_NODES, EMB_DIM, EMB_DIM);
    k_agg<<<nb_warp8, T256>>>(p_XW, p_b3, p_bufA);

    // pooling -> g_xc[:, 4096:4224]
    k_pool<<<nb_warp8, T256>>>(p_bufA, batch);
    k_pool_div<<<(N_GRAPHS * EMB_DIM + T256 - 1) / T256, T256>>>();

    // heads
    k_sgemm<false><<<dim3(EMB_DIM / 64, 1), 256>>>(p_xc, CAT_DIM, Wi, IMG_DIM,
                                                   bi, p_oi, EMB_DIM, N_GRAPHS, EMB_DIM, IMG_DIM);
    k_sgemm<false><<<dim3(EMB_DIM / 64, 1), 256>>>(p_xc, CAT_DIM, Wc, CAT_DIM,
                                                   bc, p_oc, EMB_DIM, N_GRAPHS, EMB_DIM, CAT_DIM);

    // normalize + write outputs: [oi | oc]
    k_norm<<<N_GRAPHS, EMB_DIM>>>(p_oi, out);
    k_norm<<<N_GRAPHS, EMB_DIM>>>(p_oc, out + N_GRAPHS * EMB_DIM);
    (void)in_sizes; (void)n_in; (void)out_size;
}

// round 2
// speedup vs baseline: 3.0775x; 3.0775x over previous
#include <cuda_runtime.h>
#include <cuda_bf16.h>

#define N_NODES 50000
#define N_EDGES 800000
#define N_GRAPHS 64
#define EMB_DIM 128
#define IMG_DIM 4096
#define N_TYPES 30
#define CAT_DIM (IMG_DIM + EMB_DIM)   // 4224

#define IMG_SPLITS 8
#define IMG_KC 512
#define HEAD_KC 128
#define HI_SPLITS 32                  // 4096/128
#define HC_SPLITS 33                  // 4224/128
#define IMG_BLOCKS (64 * IMG_SPLITS)  // 512
#define AGG_BLOCKS ((N_NODES + 7) / 8)// 6250

// ---------------- device scratch ------------------------------------------------
__device__ float g_dis[N_NODES];
__device__ int   g_cnt_e[N_NODES];
__device__ int   g_offs[N_NODES + 1];
__device__ int   g_cursor[N_NODES];
__device__ int2  g_epack[N_EDGES];          // (row, coef-as-int)
__device__ int   g_goff[N_GRAPHS + 1];      // graph start offsets (batch sorted)

__device__ float g_XW[N_NODES * EMB_DIM];
__device__ float g_bufA[N_NODES * EMB_DIM];
__device__ float g_bufB[N_NODES * EMB_DIM];
__device__ float g_TXW[N_TYPES * EMB_DIM];
__device__ float g_xc[N_GRAPHS * CAT_DIM];  // [xi | pooled]
__device__ float g_ipart[IMG_SPLITS * 64 * IMG_DIM];
__device__ float g_hpi[HI_SPLITS * 64 * EMB_DIM];
__device__ float g_hpc[HC_SPLITS * 64 * EMB_DIM];

// ---------------- preprocessing -------------------------------------------------
__global__ void k_init() {
    int i = blockIdx.x * blockDim.x + threadIdx.x;
    if (i < N_NODES) { g_dis[i] = 1.0f; g_cnt_e[i] = 0; g_cursor[i] = 0; }
}

// edge-indexed: deg[col]+=ew, cnt[col]++ ; node-indexed duty: graph boundaries
__global__ void k_deg(const int* __restrict__ ei, const float* __restrict__ ea,
                      const int* __restrict__ batch) {
    int i = blockIdx.x * blockDim.x + threadIdx.x;
    if (i < N_EDGES) {
        int c = ei[N_EDGES + i];
        atomicAdd(&g_dis[c], ea[i]);
        atomicAdd(&g_cnt_e[c], 1);
    }
    if (i < N_NODES) {
        int b = batch[i];
        if (i == 0) {
            for (int g = 0; g <= b; g++) g_goff[g] = 0;
        } else {
            int pb = batch[i - 1];
            for (int g = pb + 1; g <= b; g++) g_goff[g] = i;
        }
        if (i == N_NODES - 1)
            for (int g = b + 1; g <= N_GRAPHS; g++) g_goff[g] = N_NODES;
    }
}

// single block: exclusive scan of counts -> offs, plus dis = rsqrt(deg)
__global__ void k_scan() {
    __shared__ int sh[1024];
    const int C = (N_NODES + 1023) / 1024;   // 49
    int t = threadIdx.x;
    int base = t * C;
    int sum = 0;
    for (int j = 0; j < C; j++) {
        int i = base + j;
        if (i < N_NODES) sum += g_cnt_e[i];
    }
    sh[t] = sum;
    __syncthreads();
    for (int off = 1; off < 1024; off <<= 1) {
        int v = (t >= off) ? sh[t - off] : 0;
        __syncthreads();
        sh[t] += v;
        __syncthreads();
    }
    int prefix = t ? sh[t - 1] : 0;
    for (int j = 0; j < C; j++) {
        int i = base + j;
        if (i < N_NODES) { int c = g_cnt_e[i]; g_offs[i] = prefix; prefix += c; }
    }
    if (t == 1023) g_offs[N_NODES] = sh[1023];
    for (int i = t; i < N_NODES; i += 1024) g_dis[i] = rsqrtf(g_dis[i]);
}

__global__ void k_scatter(const int* __restrict__ ei, const float* __restrict__ ea) {
    int e = blockIdx.x * blockDim.x + threadIdx.x;
    if (e >= N_EDGES) return;
    int r = ei[e], c = ei[N_EDGES + e];
    float coef = g_dis[r] * ea[e] * g_dis[c];
    int pos = g_offs[c] + atomicAdd(&g_cursor[c], 1);
    g_epack[pos] = make_int2(r, __float_as_int(coef));
}

// ---------------- layer-1 table trick -------------------------------------------
__global__ void k_table_gemm(const float* __restrict__ emb, const float* __restrict__ W1) {
    __shared__ float xr[EMB_DIM];
    int t = blockIdx.x, d = threadIdx.x;
    xr[d] = emb[t * EMB_DIM + d];
    __syncthreads();
    const float* w = &W1[d * EMB_DIM];
    float s = 0.f;
    #pragma unroll 8
    for (int k = 0; k < EMB_DIM; k++) s += xr[k] * w[k];
    g_TXW[t * EMB_DIM + d] = s;
}

__global__ void k_gather(const int* __restrict__ types) {
    int t = blockIdx.x * blockDim.x + threadIdx.x;
    if (t >= N_NODES * 32) return;
    int i = t >> 5, j = (t & 31) << 2;
    *(float4*)&g_XW[i * EMB_DIM + j] = *(const float4*)&g_TXW[types[i] * EMB_DIM + j];
}

// ---------------- CSR aggregation (warp per node) -------------------------------
template <bool RELU>
__device__ __forceinline__ void agg_body(const float* __restrict__ xw,
                                         const float* __restrict__ bias,
                                         float* __restrict__ out, int bid) {
    int node = bid * 8 + ((int)threadIdx.x >> 5);
    if (node >= N_NODES) return;
    int lane = threadIdx.x & 31;
    int s = g_offs[node], e = g_offs[node + 1];
    float4 a0 = make_float4(0.f, 0.f, 0.f, 0.f);
    float4 a1 = make_float4(0.f, 0.f, 0.f, 0.f);
    int p = s;
    for (; p + 1 < e; p += 2) {
        int2 e0 = g_epack[p], e1 = g_epack[p + 1];
        float4 v0 = *(const float4*)&xw[(size_t)e0.x * EMB_DIM + lane * 4];
        float4 v1 = *(const float4*)&xw[(size_t)e1.x * EMB_DIM + lane * 4];
        float c0 = __int_as_float(e0.y), c1 = __int_as_float(e1.y);
        a0.x += c0 * v0.x; a0.y += c0 * v0.y; a0.z += c0 * v0.z; a0.w += c0 * v0.w;
        a1.x += c1 * v1.x; a1.y += c1 * v1.y; a1.z += c1 * v1.z; a1.w += c1 * v1.w;
    }
    if (p < e) {
        int2 e0 = g_epack[p];
        float4 v0 = *(const float4*)&xw[(size_t)e0.x * EMB_DIM + lane * 4];
        float c0 = __int_as_float(e0.y);
        a0.x += c0 * v0.x; a0.y += c0 * v0.y; a0.z += c0 * v0.z; a0.w += c0 * v0.w;
    }
    a0.x += a1.x; a0.y += a1.y; a0.z += a1.z; a0.w += a1.w;
    float d2 = g_dis[node]; d2 *= d2;
    float4 v = *(const float4*)&xw[(size_t)node * EMB_DIM + lane * 4];
    float4 b = *(const float4*)&bias[lane * 4];
    a0.x += d2 * v.x + b.x; a0.y += d2 * v.y + b.y;
    a0.z += d2 * v.z + b.z; a0.w += d2 * v.w + b.w;
    if (RELU) {
        a0.x = fmaxf(a0.x, 0.f); a0.y = fmaxf(a0.y, 0.f);
        a0.z = fmaxf(a0.z, 0.f); a0.w = fmaxf(a0.w, 0.f);
    }
    *(float4*)&out[(size_t)node * EMB_DIM + lane * 4] = a0;
}

template <bool RELU>
__global__ void __launch_bounds__(256) k_agg(const float* __restrict__ xw,
                                             const float* __restrict__ bias,
                                             float* __restrict__ out) {
    agg_body<RELU>(xw, bias, out, blockIdx.x);
}

// ---------------- 64x64 SGEMM tile: C = A(*,K) * B(*,K)^T -----------------------
__device__ __forceinline__ void sgemm64(const float* __restrict__ A, int lda,
                                        const float* __restrict__ B, int ldb,
                                        float* __restrict__ C, int ldc,
                                        int m0, int n0, int k0, int klen,
                                        int M, int N) {
    __shared__ float As[16][68];
    __shared__ float Bs[16][68];
    int t = threadIdx.x;
    int tn = t & 15, tm = t >> 4;
    int lrow = t >> 2, lkq = (t & 3) << 2;

    float c[4][4];
    #pragma unroll
    for (int i = 0; i < 4; i++)
        #pragma unroll
        for (int j = 0; j < 4; j++) c[i][j] = 0.f;

    for (int kk = k0; kk < k0 + klen; kk += 16) {
        float4 a;
        int am = m0 + lrow;
        if (am < M) a = *(const float4*)&A[(size_t)am * lda + kk + lkq];
        else        a = make_float4(0.f, 0.f, 0.f, 0.f);
        As[lkq + 0][lrow] = a.x; As[lkq + 1][lrow] = a.y;
        As[lkq + 2][lrow] = a.z; As[lkq + 3][lrow] = a.w;
        int bn = n0 + lrow;
        float4 b;
        if (bn < N) b = *(const float4*)&B[(size_t)bn * ldb + kk + lkq];
        else        b = make_float4(0.f, 0.f, 0.f, 0.f);
        Bs[lkq + 0][lrow] = b.x; Bs[lkq + 1][lrow] = b.y;
        Bs[lkq + 2][lrow] = b.z; Bs[lkq + 3][lrow] = b.w;
        __syncthreads();
        #pragma unroll
        for (int k = 0; k < 16; k++) {
            float4 af = *(const float4*)&As[k][tm * 4];
            float4 bf = *(const float4*)&Bs[k][tn * 4];
            c[0][0] += af.x * bf.x; c[0][1] += af.x * bf.y; c[0][2] += af.x * bf.z; c[0][3] += af.x * bf.w;
            c[1][0] += af.y * bf.x; c[1][1] += af.y * bf.y; c[1][2] += af.y * bf.z; c[1][3] += af.y * bf.w;
            c[2][0] += af.z * bf.x; c[2][1] += af.z * bf.y; c[2][2] += af.z * bf.z; c[2][3] += af.z * bf.w;
            c[3][0] += af.w * bf.x; c[3][1] += af.w * bf.y; c[3][2] += af.w * bf.z; c[3][3] += af.w * bf.w;
        }
        __syncthreads();
    }
    #pragma unroll
    for (int i = 0; i < 4; i++) {
        int m = m0 + tm * 4 + i;
        if (m >= M) continue;
        #pragma unroll
        for (int j = 0; j < 4; j++)
            C[(size_t)m * ldc + n0 + tn * 4 + j] = c[i][j];
    }
}

// node-layer GEMM: [N_NODES,128] x [128,128]^T
__global__ void __launch_bounds__(256) k_gemm128(const float* __restrict__ A,
                                                 const float* __restrict__ B,
                                                 float* __restrict__ C) {
    sgemm64(A, EMB_DIM, B, EMB_DIM, C, EMB_DIM,
            blockIdx.y * 64, blockIdx.x * 64, 0, EMB_DIM, N_NODES, EMB_DIM);
}

// generic split-K into partial buffer (M = 64 always)
__global__ void __launch_bounds__(256) k_splitk(const float* __restrict__ A, int lda,
                                                const float* __restrict__ B, int ldb,
                                                float* __restrict__ part, int N, int KC) {
    int z = blockIdx.z;
    sgemm64(A, lda, B, ldb, part + (size_t)z * 64 * N, N,
            0, blockIdx.x * 64, z * KC, KC, 64, N);
}

// fused: image split-K GEMM (blocks 0..511) + layer-1 aggregation (rest)
__global__ void __launch_bounds__(256) k_fused(const float* __restrict__ images,
                                               const float* __restrict__ W_img,
                                               const float* __restrict__ b1) {
    if (blockIdx.x < IMG_BLOCKS) {
        int ntile = blockIdx.x & 63, z = blockIdx.x >> 6;
        sgemm64(images, IMG_DIM, W_img, IMG_DIM,
                g_ipart + (size_t)z * 64 * IMG_DIM, IMG_DIM,
                0, ntile * 64, z * IMG_KC, IMG_KC, 64, IMG_DIM);
    } else {
        agg_body<true>(g_XW, b1, g_bufA, blockIdx.x - IMG_BLOCKS);
    }
}

__global__ void k_img_reduce(const float* __restrict__ b_img) {
    int i = blockIdx.x * blockDim.x + threadIdx.x;
    if (i >= 64 * IMG_DIM) return;
    int m = i >> 12, n = i & (IMG_DIM - 1);
    float v = b_img[n];
    #pragma unroll
    for (int z = 0; z < IMG_SPLITS; z++)
        v += g_ipart[((size_t)z * 64 + m) * IMG_DIM + n];
    g_xc[m * CAT_DIM + n] = v;
}

// segment mean-pool per graph (batch sorted -> contiguous ranges)
__global__ void __launch_bounds__(512) k_pool_seg(const float* __restrict__ xg) {
    __shared__ float sh[512];
    int g = blockIdx.x;
    int d = threadIdx.x & 127, l4 = threadIdx.x >> 7;
    int s = g_goff[g], e = g_goff[g + 1];
    float acc = 0.f;
    for (int i = s + l4; i < e; i += 4) acc += xg[(size_t)i * EMB_DIM + d];
    sh[threadIdx.x] = acc;
    __syncthreads();
    if (threadIdx.x < 128) {
        float v = sh[d] + sh[128 + d] + sh[256 + d] + sh[384 + d];
        float c = fmaxf((float)(e - s), 1.f);
        g_xc[g * CAT_DIM + IMG_DIM + d] = v / c;
    }
}

// reduce head partials + bias + row L2-normalize, write final output
__global__ void k_headnorm(const float* __restrict__ bi, const float* __restrict__ bc,
                           float* __restrict__ out) {
    __shared__ float sh[4];
    int which = blockIdx.x >> 6, m = blockIdx.x & 63, n = threadIdx.x;
    float v;
    if (which == 0) {
        v = bi[n];
        #pragma unroll
        for (int z = 0; z < HI_SPLITS; z++) v += g_hpi[(z * 64 + m) * EMB_DIM + n];
    } else {
        v = bc[n];
        #pragma unroll
        for (int z = 0; z < HC_SPLITS; z++) v += g_hpc[(z * 64 + m) * EMB_DIM + n];
    }
    float s = v * v;
    #pragma unroll
    for (int o = 16; o; o >>= 1) s += __shfl_xor_sync(0xffffffffu, s, o);
    if ((n & 31) == 0) sh[n >> 5] = s;
    __syncthreads();
    float tot = sh[0] + sh[1] + sh[2] + sh[3];
    out[blockIdx.x * EMB_DIM + n] = v * rsqrtf(tot);
}

// ---------------- host ----------------------------------------------------------
extern "C" void kernel_launch(void* const* d_in, const int* in_sizes, int n_in,
                              void* d_out, int out_size) {
    const float* images = (const float*)d_in[0];
    const int*   ntypes = (const int*)  d_in[1];
    const int*   eidx   = (const int*)  d_in[2];
    const float* eattr  = (const float*)d_in[3];
    const int*   batch  = (const int*)  d_in[4];
    const float* emb    = (const float*)d_in[5];
    const float* W_img  = (const float*)d_in[6];
    const float* b_img  = (const float*)d_in[7];
    const float* b1     = (const float*)d_in[9];
    const float* W2     = (const float*)d_in[10];
    const float* b2     = (const float*)d_in[11];
    const float* W3     = (const float*)d_in[12];
    const float* b3     = (const float*)d_in[13];
    const float* Wi     = (const float*)d_in[14];
    const float* bi     = (const float*)d_in[15];
    const float* Wc     = (const float*)d_in[16];
    const float* bc     = (const float*)d_in[17];
    const float* W1     = (const float*)d_in[8];
    float* out = (float*)d_out;

    float *p_XW, *p_bufA, *p_bufB, *p_xc, *p_hpi, *p_hpc;
    cudaGetSymbolAddress((void**)&p_XW,   g_XW);
    cudaGetSymbolAddress((void**)&p_bufA, g_bufA);
    cudaGetSymbolAddress((void**)&p_bufB, g_bufB);
    cudaGetSymbolAddress((void**)&p_xc,   g_xc);
    cudaGetSymbolAddress((void**)&p_hpi,  g_hpi);
    cudaGetSymbolAddress((void**)&p_hpc,  g_hpc);

    const int T = 256;
    int nb_nodes = (N_NODES + T - 1) / T;
    int nb_edges = (N_EDGES + T - 1) / T;

    // graph preprocessing
    k_init<<<nb_nodes, T>>>();
    k_deg<<<nb_edges, T>>>(eidx, eattr, batch);
    k_scan<<<1, 1024>>>();
    k_scatter<<<nb_edges, T>>>(eidx, eattr);

    // layer 1 inputs: table GEMM + gather
    k_table_gemm<<<N_TYPES, EMB_DIM>>>(emb, W1);
    k_gather<<<(N_NODES * 32 + T - 1) / T, T>>>(ntypes);

    // fused: image split-K GEMM + layer-1 aggregation (relu)
    k_fused<<<IMG_BLOCKS + AGG_BLOCKS, T>>>(images, W_img, b1);
    k_img_reduce<<<(64 * IMG_DIM + T - 1) / T, T>>>(b_img);

    // layer 2
    k_gemm128<<<dim3(2, (N_NODES + 63) / 64), T>>>(p_bufA, W2, p_XW);
    k_agg<true><<<AGG_BLOCKS, T>>>(p_XW, b2, p_bufB);

    // layer 3
    k_gemm128<<<dim3(2, (N_NODES + 63) / 64), T>>>(p_bufB, W3, p_XW);
    k_agg<false><<<AGG_BLOCKS, T>>>(p_XW, b3, p_bufA);

    // pooling -> g_xc[:, 4096:]
    k_pool_seg<<<N_GRAPHS, 512>>>(p_bufA);

    // heads (split-K) + fused reduce/normalize
    k_splitk<<<dim3(2, 1, HI_SPLITS), T>>>(p_xc, CAT_DIM, Wi, IMG_DIM, p_hpi, EMB_DIM, HEAD_KC);
    k_splitk<<<dim3(2, 1, HC_SPLITS), T>>>(p_xc, CAT_DIM, Wc, CAT_DIM, p_hpc, EMB_DIM, HEAD_KC);
    k_headnorm<<<2 * 64, EMB_DIM>>>(bi, bc, out);

    (void)in_sizes; (void)n_in; (void)out_size;
}